// round 10
// baseline (speedup 1.0000x reference)
#include <cuda_runtime.h>
#include <cuda_bf16.h>
#include <cstdint>

#define N_TRIALS   8
#define T_TOTAL    600
#define N_NEURONS  30000
#define T_USE      500
#define N_SAMPLES  50
#define MAX_COUNT  200
#define N_BINS     16
#define EPS        1e-7f
#define SYNC_COST  10.0f

#define NJ          8                 // per-sample id chunks (dynamic split of [0,cnt))
#define TS          4                 // t-slices (128 timesteps each)
#define JMAX        25                // ceil(MAX_COUNT/NJ)
#define BLOCKS_PER_SAMPLE (NJ * TS)   // 32

__constant__ int c_bins[N_BINS] = {1,1,2,3,4,6,9,13,18,26,38,55,78,113,162,234};

// Scratch (device globals: allocation is forbidden)
__device__ float        g_part[NJ * N_SAMPLES * T_USE];  // partial gather sums
__device__ float        g_fano[N_BINS * N_SAMPLES];      // per-(bin,sample) fano
__device__ unsigned int g_scnt[N_SAMPLES];               // per-sample completion counters
__device__ unsigned int g_ticket;                        // sample-finisher ticket
// all counters reset in-kernel by their finishers -> graph-replay safe

__device__ __forceinline__ void cp_async4(uint32_t smem_byte_addr, const void* gptr) {
    asm volatile("cp.async.ca.shared.global [%0], [%1], 4;"
                 :: "r"(smem_byte_addr), "l"(gptr));
}

// ---------------------------------------------------------------------------
// Fused kernel. Block = (sample, j-chunk, t-slice), 128 threads, 1600 blocks.
// R9 falsified the occupancy theory (occ 15.5%->59.6%, DRAM flat at 48%):
// the gather is L1-MSHR-limited (~64 misses in flight/SM). cp.async (LDGSTS)
// has NO observed in-flight depth cap on B300, so each thread parks its whole
// id chunk (<=25 scattered 4B copies) in flight -> thousands of lines/SM in
// flight -> DRAM becomes byte-bound instead of latency-bound.
//  A) gather: thread owns one timestep; cp.async all ids -> smem, wait, sum.
//  B) block completing its sample (counter hits 32) combines the 8 partials
//     into smem and computes all 16 bins' fanos (4 warps x 4 bins).
//  C) last sample-finisher (ticket) reduces g_fano -> scalar loss.
// mask is prefix-form (arange < count) => effective count = sum(mask);
// ids[0:cnt] are exactly the active ids (duplicates preserved).
// sample_ids arrives as int32 (JAX x64-disabled demotes int64 -> int32).
// ---------------------------------------------------------------------------
__global__ void __launch_bounds__(128)
fused_kernel(const float* __restrict__ spikes,
             const int*   __restrict__ trials,
             const int*   __restrict__ ids,
             const float* __restrict__ mask,
             const float* __restrict__ exp_fanos,
             float*       __restrict__ out)
{
    __shared__ float s_buf[128 * JMAX];     // cp.async landing zone (stride 25: conflict-free)
    __shared__ int   s_ids[JMAX];
    __shared__ int   s_cnt;
    __shared__ float s_row[T_USE];
    __shared__ bool  s_sample_done, s_all_done;

    const int s    = blockIdx.x;
    const int jc   = blockIdx.y;
    const int ts   = blockIdx.z;
    const int tid  = threadIdx.x;
    const int lane = tid & 31;
    const int wid  = tid >> 5;

    // ---- effective count + this chunk's ids ----
    if (tid == 0) s_cnt = 0;
    __syncthreads();
    int local = 0;
    #pragma unroll
    for (int j = tid; j < MAX_COUNT; j += 128)
        if (mask[s * MAX_COUNT + j] != 0.0f) local++;
    if (local) atomicAdd(&s_cnt, local);
    __syncthreads();

    const int cnt = s_cnt;
    const int lo  = (jc * cnt) / NJ;
    const int m   = ((jc + 1) * cnt) / NJ - lo;    // <= 25
    if (tid < m)
        s_ids[tid] = ids[s * MAX_COUNT + lo + tid];
    __syncthreads();

    // ---- A) gather via deep cp.async pipeline ----
    const int t = ts * 128 + tid;
    if (t < T_USE) {
        const float* __restrict__ base =
            spikes + (size_t)trials[s] * ((size_t)T_TOTAL * N_NEURONS)
                   + (size_t)t * N_NEURONS;

        const uint32_t buf = (uint32_t)__cvta_generic_to_shared(s_buf)
                           + (uint32_t)(tid * JMAX) * 4u;
        for (int j = 0; j < m; ++j)
            cp_async4(buf + j * 4u, base + s_ids[j]);
        asm volatile("cp.async.commit_group;");
        asm volatile("cp.async.wait_group 0;" ::: "memory");

        const float* mybuf = s_buf + tid * JMAX;
        float acc = 0.0f;
        int j = 0;
        for (; j + 4 <= m; j += 4) {
            float v0 = mybuf[j], v1 = mybuf[j+1], v2 = mybuf[j+2], v3 = mybuf[j+3];
            acc += (v0 + v1) + (v2 + v3);
        }
        for (; j < m; ++j) acc += mybuf[j];

        g_part[(jc * N_SAMPLES + s) * T_USE + t] = acc;
    }

    // ---- B) sample-completion handoff ----
    __threadfence();
    __syncthreads();
    if (tid == 0) {
        unsigned int old = atomicAdd(&g_scnt[s], 1u);
        s_sample_done = (old == BLOCKS_PER_SAMPLE - 1);
        if (s_sample_done) g_scnt[s] = 0;     // reset for next graph replay
    }
    __syncthreads();
    if (!s_sample_done) return;

    // this block is the last of its sample: combine partials -> smem row
    for (int i = tid; i < T_USE; i += 128) {
        float v = 0.0f;
        #pragma unroll
        for (int c = 0; c < NJ; ++c)
            v += g_part[(c * N_SAMPLES + s) * T_USE + i];
        s_row[i] = v;
    }
    __syncthreads();

    // 4 warps x 4 bins: single-pass sum / sum-of-squares per bin
    #pragma unroll
    for (int rep = 0; rep < 4; ++rep) {
        const int b  = wid + rep * 4;
        const int bs = c_bins[b];
        const int nb = T_USE / bs;

        float sum = 0.0f, sumsq = 0.0f;
        for (int k = lane; k < nb; k += 32) {
            const float* rk = s_row + k * bs;
            float c = 0.0f;
            int u = 0;
            for (; u + 4 <= bs; u += 4) {
                float q0 = rk[u], q1 = rk[u+1], q2 = rk[u+2], q3 = rk[u+3];
                c += (q0 + q1) + (q2 + q3);
            }
            for (; u < bs; ++u) c += rk[u];
            sum   += c;
            sumsq += c * c;
        }
        #pragma unroll
        for (int off = 16; off > 0; off >>= 1) {
            sum   += __shfl_down_sync(0xffffffff, sum,   off);
            sumsq += __shfl_down_sync(0xffffffff, sumsq, off);
        }
        if (lane == 0) {
            const float mean = sum / (float)nb;
            const float var  = sumsq / (float)nb - mean * mean;
            g_fano[b * N_SAMPLES + s] = var / fmaxf(mean, EPS);
        }
    }

    // ---- C) last sample-finisher reduces g_fano -> scalar loss ----
    __threadfence();
    __syncthreads();
    if (tid == 0) {
        unsigned int old = atomicAdd(&g_ticket, 1u);
        s_all_done = (old == N_SAMPLES - 1);
        if (s_all_done) g_ticket = 0;         // reset for next graph replay
    }
    __syncthreads();

    if (s_all_done && wid == 0) {
        float d2 = 0.0f;
        if (lane < N_BINS) {
            float fsum = 0.0f;
            for (int q = 0; q < N_SAMPLES; ++q)
                fsum += g_fano[lane * N_SAMPLES + q];
            const float fm = fsum / (float)N_SAMPLES;
            const float d  = exp_fanos[lane] - fm;
            d2 = d * d;
        }
        #pragma unroll
        for (int off = 16; off > 0; off >>= 1)
            d2 += __shfl_down_sync(0xffffffff, d2, off);
        if (lane == 0)
            out[0] = SYNC_COST * (d2 / (float)N_BINS);
    }
}

// ---------------------------------------------------------------------------
// Inputs (metadata order):
//   0: spikes float32 [8,600,30000]   1: experimental_fanos_mean float32 [16]
//   2: sample_trials int32 [50]       3: sample_ids int32 [50,200]
//   4: sample_mask float32 [50,200]   out: float32 scalar
// ---------------------------------------------------------------------------
extern "C" void kernel_launch(void* const* d_in, const int* in_sizes, int n_in,
                              void* d_out, int out_size)
{
    const float* spikes = (const float*)d_in[0];
    const float* expf_  = (const float*)d_in[1];
    const int*   trials = (const int*)d_in[2];
    const int*   ids    = (const int*)d_in[3];
    const float* mask   = (const float*)d_in[4];
    float*       out    = (float*)d_out;

    dim3 grid(N_SAMPLES, NJ, TS);
    fused_kernel<<<grid, 128>>>(spikes, trials, ids, mask, expf_, out);
}

// round 11
// speedup vs baseline: 1.4718x; 1.4718x over previous
#include <cuda_runtime.h>
#include <cuda_bf16.h>
#include <cstdint>

#define N_TRIALS   8
#define T_TOTAL    600
#define N_NEURONS  30000
#define T_USE      500
#define N_SAMPLES  50
#define MAX_COUNT  200
#define N_BINS     16
#define EPS        1e-7f
#define SYNC_COST  10.0f

#define NJ          8                 // per-sample id chunks (dynamic split of [0,cnt))
#define JMAX        32                // >= ceil(MAX_COUNT/NJ) = 25
#define SORT_N      256               // bitonic size (>= MAX_COUNT, pow2)
#define FANO_BLOCKS 100               // (sample, bin-half): 50 x 2

__constant__ int c_bins[N_BINS] = {1,1,2,3,4,6,9,13,18,26,38,55,78,113,162,234};

// Scratch (device globals: allocation is forbidden)
__device__ int          g_sids[N_SAMPLES * SORT_N];      // sorted active ids per sample
__device__ int          g_cnt [N_SAMPLES];               // effective counts
__device__ float        g_part[NJ * N_SAMPLES * T_USE];  // partial gather sums
__device__ float        g_fano[N_BINS * N_SAMPLES];      // per-(bin,sample) fano
__device__ unsigned int g_ticket;                        // last-block ticket (self-resets)

// ---------------------------------------------------------------------------
// Phase 0: per-sample id sort. One block (256 thr) per sample.
// mask is prefix-form (arange < count) => effective count = sum(mask);
// ids[0:cnt] are the active ids. Masked-out slots -> INT_MAX, bitonic-sort
// ascending => g_sids[s][0:cnt] = active ids in ASCENDING order (dups kept).
// Sorted order gives the gather DRAM row-buffer locality: an 8-wide id batch
// spans ~10KB instead of ~3.8MB, so each opened DRAM row is reused ~8x.
// sample_ids arrives as int32 (JAX x64-disabled demotes int64 -> int32).
// ---------------------------------------------------------------------------
__global__ void __launch_bounds__(SORT_N)
sort_kernel(const int* __restrict__ ids, const float* __restrict__ mask)
{
    __shared__ int s_key[SORT_N];
    __shared__ int s_cnt;

    const int s   = blockIdx.x;
    const int tid = threadIdx.x;

    if (tid == 0) s_cnt = 0;
    __syncthreads();

    const bool in200 = (tid < MAX_COUNT);
    const bool active = in200 && (mask[s * MAX_COUNT + tid] != 0.0f);
    // ballot-count actives (prefix mask -> contiguous, but count generally)
    const unsigned bal = __ballot_sync(0xffffffff, active);
    if ((tid & 31) == 0 && bal) atomicAdd(&s_cnt, __popc(bal));
    __syncthreads();
    const int cnt = s_cnt;

    s_key[tid] = (in200 && tid < cnt) ? ids[s * MAX_COUNT + tid] : 0x7FFFFFFF;
    __syncthreads();

    // bitonic sort ascending, 256 elements / 256 threads
    for (int k = 2; k <= SORT_N; k <<= 1) {
        for (int j = k >> 1; j > 0; j >>= 1) {
            const int ixj = tid ^ j;
            if (ixj > tid) {
                const bool up = ((tid & k) == 0);
                const int a = s_key[tid], b = s_key[ixj];
                if ((a > b) == up) { s_key[tid] = b; s_key[ixj] = a; }
            }
            __syncthreads();
        }
    }

    g_sids[s * SORT_N + tid] = s_key[tid];
    if (tid == 0) g_cnt[s] = cnt;
}

// ---------------------------------------------------------------------------
// Phase 1: gather partial sums (R4 topology + SORTED ids).
// Block = (sample, t-chunk, j-chunk); thread owns one t; 8-wide unroll over
// consecutive sorted ids -> 8 nearby columns per opened DRAM row.
// ---------------------------------------------------------------------------
__global__ void __launch_bounds__(128)
gather_kernel(const float* __restrict__ spikes,
              const int*   __restrict__ trials)
{
    __shared__ int s_ids[JMAX];

    const int s   = blockIdx.x;
    const int jc  = blockIdx.z;
    const int tid = threadIdx.x;

    const int cnt = g_cnt[s];
    const int lo  = (jc * cnt) / NJ;
    const int m   = ((jc + 1) * cnt) / NJ - lo;    // <= 25
    if (tid < m)
        s_ids[tid] = g_sids[s * SORT_N + lo + tid];
    __syncthreads();

    const int t = blockIdx.y * 128 + tid;
    if (t >= T_USE) return;

    float acc = 0.0f;
    if (m > 0) {
        const float* __restrict__ base =
            spikes + (size_t)trials[s] * ((size_t)T_TOTAL * N_NEURONS)
                   + (size_t)t * N_NEURONS;
        int j = 0;
        for (; j + 8 <= m; j += 8) {
            float v0 = __ldg(base + s_ids[j + 0]);
            float v1 = __ldg(base + s_ids[j + 1]);
            float v2 = __ldg(base + s_ids[j + 2]);
            float v3 = __ldg(base + s_ids[j + 3]);
            float v4 = __ldg(base + s_ids[j + 4]);
            float v5 = __ldg(base + s_ids[j + 5]);
            float v6 = __ldg(base + s_ids[j + 6]);
            float v7 = __ldg(base + s_ids[j + 7]);
            acc += ((v0 + v1) + (v2 + v3)) + ((v4 + v5) + (v6 + v7));
        }
        for (; j < m; ++j) acc += __ldg(base + s_ids[j]);
    }
    g_part[(jc * N_SAMPLES + s) * T_USE + t] = acc;
}

// ---------------------------------------------------------------------------
// Phase 2: block = (sample, bin-half); 100 blocks x 256 threads.
// Combine partials -> smem row; 8 warps each do one bin (single-pass
// sum/sumsq). Last block (ticket) computes MSE scalar and resets the ticket.
// ---------------------------------------------------------------------------
__global__ void __launch_bounds__(256)
fano_kernel(const float* __restrict__ exp_fanos, float* __restrict__ out)
{
    __shared__ float s_row[T_USE];
    __shared__ bool  s_last;

    const int s    = blockIdx.x >> 1;
    const int half = blockIdx.x & 1;
    const int tid  = threadIdx.x;
    const int lane = tid & 31;
    const int wid  = tid >> 5;

    for (int i = tid; i < T_USE; i += 256) {
        float v = 0.0f;
        #pragma unroll
        for (int c = 0; c < NJ; ++c)
            v += g_part[(c * N_SAMPLES + s) * T_USE + i];
        s_row[i] = v;
    }
    __syncthreads();

    {
        const int b  = half * 8 + wid;
        const int bs = c_bins[b];
        const int nb = T_USE / bs;

        float sum = 0.0f, sumsq = 0.0f;
        for (int k = lane; k < nb; k += 32) {
            const float* rk = s_row + k * bs;
            float c = 0.0f;
            int u = 0;
            for (; u + 4 <= bs; u += 4) {
                float a0 = rk[u], a1 = rk[u+1], a2 = rk[u+2], a3 = rk[u+3];
                c += (a0 + a1) + (a2 + a3);
            }
            for (; u < bs; ++u) c += rk[u];
            sum   += c;
            sumsq += c * c;
        }
        #pragma unroll
        for (int off = 16; off > 0; off >>= 1) {
            sum   += __shfl_down_sync(0xffffffff, sum,   off);
            sumsq += __shfl_down_sync(0xffffffff, sumsq, off);
        }
        if (lane == 0) {
            const float mean = sum / (float)nb;
            const float var  = sumsq / (float)nb - mean * mean;
            g_fano[b * N_SAMPLES + s] = var / fmaxf(mean, EPS);
        }
    }

    // last-block reduction -> scalar loss
    __threadfence();
    __syncthreads();
    if (tid == 0) {
        unsigned int old = atomicAdd(&g_ticket, 1u);
        s_last = (old == FANO_BLOCKS - 1);
        if (s_last) g_ticket = 0;          // reset for next graph replay
    }
    __syncthreads();

    if (s_last && wid == 0) {
        float d2 = 0.0f;
        if (lane < N_BINS) {
            float fsum = 0.0f;
            for (int q = 0; q < N_SAMPLES; ++q)
                fsum += g_fano[lane * N_SAMPLES + q];
            const float fm = fsum / (float)N_SAMPLES;
            const float d  = exp_fanos[lane] - fm;
            d2 = d * d;
        }
        #pragma unroll
        for (int off = 16; off > 0; off >>= 1)
            d2 += __shfl_down_sync(0xffffffff, d2, off);
        if (lane == 0)
            out[0] = SYNC_COST * (d2 / (float)N_BINS);
    }
}

// ---------------------------------------------------------------------------
// Inputs (metadata order):
//   0: spikes float32 [8,600,30000]   1: experimental_fanos_mean float32 [16]
//   2: sample_trials int32 [50]       3: sample_ids int32 [50,200]
//   4: sample_mask float32 [50,200]   out: float32 scalar
// ---------------------------------------------------------------------------
extern "C" void kernel_launch(void* const* d_in, const int* in_sizes, int n_in,
                              void* d_out, int out_size)
{
    const float* spikes = (const float*)d_in[0];
    const float* expf_  = (const float*)d_in[1];
    const int*   trials = (const int*)d_in[2];
    const int*   ids    = (const int*)d_in[3];
    const float* mask   = (const float*)d_in[4];
    float*       out    = (float*)d_out;

    sort_kernel<<<N_SAMPLES, SORT_N>>>(ids, mask);
    dim3 grid(N_SAMPLES, (T_USE + 127) / 128, NJ);
    gather_kernel<<<grid, 128>>>(spikes, trials);
    fano_kernel<<<FANO_BLOCKS, 256>>>(expf_, out);
}